// round 5
// baseline (speedup 1.0000x reference)
#include <cuda_runtime.h>
#include <math.h>

// RoIAlign_withBanks: N=2000 boxes, C=256, G=7, 6 FPN levels, dims {38,19,10,5,3,1}.
// Output [N, C, 7, 7] fp32.
//
// R5: single-wave residency. TPB=128, one box per block -> 2000*128 = 256k
// threads < 148 SM * 2048 = 303k: the ENTIRE grid is co-resident (one wave,
// no block churn, no wave-quantization tail), giving 13-14 independent
// 4-warp blocks per SM to hide the scattered-load latency.
// Body = R3 scheme: 49 cells precomputed to shared {int4 offsets, float4
// folded weights}; each thread serves 4 channel groups {c, c+64, c+128,
// c+192} per cell -> 1 shared pair per 4 outputs, 4 FFMA/output, coalesced
// stores. __launch_bounds__(128,16) caps regs at 32 to keep 16 blocks/SM.

#define G_POOL 7
#define CELLS 49
#define QCH 64                  // channels per group (256/4)
#define QELEMS (QCH * CELLS)    // 3136
#define TPB 128
#define FULL_ITERS 24           // 24*128 = 3072
#define REM 64                  // 3136 - 3072

__global__ __launch_bounds__(TPB, 16) void roialign_banks_kernel(
    const float* __restrict__ boxes,
    const float* __restrict__ f0, const float* __restrict__ f1,
    const float* __restrict__ f2, const float* __restrict__ f3,
    const float* __restrict__ f4, const float* __restrict__ f5,
    float* __restrict__ out)
{
    const int n = blockIdx.x;
    const int t = threadIdx.x;

    const float bx1 = boxes[4 * n + 0];
    const float by1 = boxes[4 * n + 1];
    const float bx2 = boxes[4 * n + 2];
    const float by2 = boxes[4 * n + 3];

    // Level: clip(floor(5 + log2(sqrt(w*h))), 0, 5)
    const float avg = sqrtf((bx2 - bx1) * (by2 - by1));
    const float lf  = floorf(5.0f + log2f(avg));
    const int lvl   = (int)fminf(fmaxf(lf, 0.0f), 5.0f);

    const float* fm;
    int D;
    switch (lvl) {
        case 0:  fm = f0; D = 38; break;
        case 1:  fm = f1; D = 19; break;
        case 2:  fm = f2; D = 10; break;
        case 3:  fm = f3; D = 5;  break;
        case 4:  fm = f4; D = 3;  break;
        default: fm = f5; D = 1;  break;
    }
    const int DD = D * D;

    __shared__ int4   s_off[CELLS];   // {o00, o10, o01, o11} plane offsets
    __shared__ float4 s_w[CELLS];     // folded corner weights

    if (t < CELLS) {
        const int i = t / G_POOL;     // x-grid index (fmap rows)
        const int j = t % G_POOL;     // y-grid index (fmap cols)
        float xr = fminf(fmaxf(bx1 + (float)i * (bx2 - bx1) / 6.0f, 0.0f), 1.0f);
        float yr = fminf(fmaxf(by1 + (float)j * (by2 - by1) / 6.0f, 0.0f), 1.0f);
        float ux = xr * (float)(D - 1);
        float uy = yr * (float)(D - 1);
        float fx = floorf(ux);
        float fy = floorf(uy);
        int ix0 = (int)fx;
        int iy0 = (int)fy;
        int ix1 = (int)ceilf(ux);
        int iy1 = (int)ceilf(uy);
        // ceil-floor in {0,1} -> reference weights collapse to (1-frac, frac)
        float px0 = 1.0f - (ux - fx);
        float py0 = 1.0f - (uy - fy);
        float px1 = 1.0f - px0;
        float py1 = 1.0f - py0;
        s_off[t] = make_int4(ix0 * D + iy0, ix1 * D + iy0,
                             ix0 * D + iy1, ix1 * D + iy1);
        s_w[t]   = make_float4(px0 * py0, px1 * py0, px0 * py1, px1 * py1);
    }
    __syncthreads();

    float* __restrict__ op = out + (size_t)n * (4 * QELEMS) + t;

    // k = t + 128*e over [0, 3136). 128 = 2*49 + 30.
    int c   = t / CELLS;              // 0..2
    int pos = t - c * CELLS;
    const int strideCh = QCH * DD;    // 64 channel planes

    const float* p0 = fm + c * DD;
    const float* p1 = p0 + strideCh;
    const float* p2 = p0 + 2 * strideCh;
    const float* p3 = p0 + 3 * strideCh;

#pragma unroll 2
    for (int e = 0; e < FULL_ITERS; ++e) {
        const int4   o = s_off[pos];
        const float4 w = s_w[pos];

        float r0 = w.x * __ldg(p0 + o.x) + w.y * __ldg(p0 + o.y)
                 + w.z * __ldg(p0 + o.z) + w.w * __ldg(p0 + o.w);
        float r1 = w.x * __ldg(p1 + o.x) + w.y * __ldg(p1 + o.y)
                 + w.z * __ldg(p1 + o.z) + w.w * __ldg(p1 + o.w);
        float r2 = w.x * __ldg(p2 + o.x) + w.y * __ldg(p2 + o.y)
                 + w.z * __ldg(p2 + o.z) + w.w * __ldg(p2 + o.w);
        float r3 = w.x * __ldg(p3 + o.x) + w.y * __ldg(p3 + o.y)
                 + w.z * __ldg(p3 + o.z) + w.w * __ldg(p3 + o.w);

        op[0]          = r0;
        op[QELEMS]     = r1;
        op[2 * QELEMS] = r2;
        op[3 * QELEMS] = r3;

        // advance by 128: c += 2, pos += 30, wrap at most once
        pos += 30;
        int adv = 2 * DD;
        if (pos >= CELLS) { pos -= CELLS; adv += DD; }
        p0 += adv; p1 += adv; p2 += adv; p3 += adv;
        op += TPB;
    }

    // remainder: k = 3072 + t for t < 64
    if (t < REM) {
        const int4   o = s_off[pos];
        const float4 w = s_w[pos];
        float r0 = w.x * __ldg(p0 + o.x) + w.y * __ldg(p0 + o.y)
                 + w.z * __ldg(p0 + o.z) + w.w * __ldg(p0 + o.w);
        float r1 = w.x * __ldg(p1 + o.x) + w.y * __ldg(p1 + o.y)
                 + w.z * __ldg(p1 + o.z) + w.w * __ldg(p1 + o.w);
        float r2 = w.x * __ldg(p2 + o.x) + w.y * __ldg(p2 + o.y)
                 + w.z * __ldg(p2 + o.z) + w.w * __ldg(p2 + o.w);
        float r3 = w.x * __ldg(p3 + o.x) + w.y * __ldg(p3 + o.y)
                 + w.z * __ldg(p3 + o.z) + w.w * __ldg(p3 + o.w);
        op[0]          = r0;
        op[QELEMS]     = r1;
        op[2 * QELEMS] = r2;
        op[3 * QELEMS] = r3;
    }
}

extern "C" void kernel_launch(void* const* d_in, const int* in_sizes, int n_in,
                              void* d_out, int out_size)
{
    const int N = in_sizes[0] / 4;
    roialign_banks_kernel<<<N, TPB>>>(
        (const float*)d_in[0],
        (const float*)d_in[1], (const float*)d_in[2], (const float*)d_in[3],
        (const float*)d_in[4], (const float*)d_in[5], (const float*)d_in[6],
        (float*)d_out);
}

// round 7
// speedup vs baseline: 1.7975x; 1.7975x over previous
#include <cuda_runtime.h>
#include <math.h>

// RoIAlign_withBanks: N=2000 boxes, C=256, G=7, 6 FPN levels, dims {38,19,10,5,3,1}.
// Output [N, C, 7, 7] fp32.
//
// R6/R7: layout-transpose + dedup-gather.
//  Kernel 1: transpose all fmaps [C,D,D] -> g_ftrans[pos][C] (2MB scratch).
//  Kernel 2: per box, the 7x7 grid touches only P (<=42, proven) unique fmap
//    points. Gather P x 128-channel chunks into shared (coalesced LDG,
//    conflict-free STS), then each thread (fixed cell, c0=t/49) samples 4
//    channels per LDS.128 with register-resident corner offsets + folded
//    weights: 1 LDS + 4 FFMA + 1 STG per output element, coalesced stores.

#define G_POOL 7
#define CELLS  49
#define NCH    256
#define TPB    196
#define PCAP   64          // max unique patch points (math bound 42)
#define CPAD   132         // padded channel stride (128 + 4): 16B aligned
#define CHUNK  128         // channels per chunk
#define NPOS   1940        // 1444+361+100+25+9+1

__device__ __align__(16) float g_ftrans[NPOS * NCH];   // [pos][channel]

__global__ void transpose_fmaps_kernel(
    const float* __restrict__ f0, const float* __restrict__ f1,
    const float* __restrict__ f2, const float* __restrict__ f3,
    const float* __restrict__ f4, const float* __restrict__ f5)
{
    const int p = blockIdx.x;          // global position index
    const float* fm; int DD, lp;
    if      (p < 1444) { fm = f0; DD = 1444; lp = p; }
    else if (p < 1805) { fm = f1; DD = 361;  lp = p - 1444; }
    else if (p < 1905) { fm = f2; DD = 100;  lp = p - 1805; }
    else if (p < 1930) { fm = f3; DD = 25;   lp = p - 1905; }
    else if (p < 1939) { fm = f4; DD = 9;    lp = p - 1930; }
    else               { fm = f5; DD = 1;    lp = 0; }
    g_ftrans[p * NCH + threadIdx.x] = fm[threadIdx.x * DD + lp];
}

__device__ __forceinline__ int nth_set_bit(unsigned long long m, int n) {
    for (int k = 0; k < n; ++k) m &= m - 1;
    return __ffsll(m) - 1;
}

__global__ __launch_bounds__(TPB) void roialign_banks_kernel(
    const float* __restrict__ boxes,
    float* __restrict__ out)
{
    __shared__ __align__(16) float s_patch[PCAP * CPAD];   // ~33 KB
    __shared__ int   s_gidx[PCAP];
    __shared__ int   s_ix0[G_POOL], s_ix1[G_POOL], s_iy0[G_POOL], s_iy1[G_POOL];
    __shared__ float s_px0[G_POOL], s_py0[G_POOL];
    __shared__ unsigned long long s_mx, s_my;
    __shared__ int s_UYn, s_P;

    const int n = blockIdx.x;
    const int t = threadIdx.x;

    const float bx1 = boxes[4 * n + 0];
    const float by1 = boxes[4 * n + 1];
    const float bx2 = boxes[4 * n + 2];
    const float by2 = boxes[4 * n + 3];

    // Level: clip(floor(5 + log2(sqrt(w*h))), 0, 5)
    const float avg = sqrtf((bx2 - bx1) * (by2 - by1));
    const float lf  = floorf(5.0f + log2f(avg));
    const int lvl   = (int)fminf(fmaxf(lf, 0.0f), 5.0f);

    int D, gbase;
    switch (lvl) {
        case 0:  D = 38; gbase = 0;    break;
        case 1:  D = 19; gbase = 1444; break;
        case 2:  D = 10; gbase = 1805; break;
        case 3:  D = 5;  gbase = 1905; break;
        case 4:  D = 3;  gbase = 1930; break;
        default: D = 1;  gbase = 1939; break;
    }

    // --- per-axis grid coords (two warps in parallel) ---
    if (t < G_POOL) {
        float xr = fminf(fmaxf(bx1 + (float)t * (bx2 - bx1) / 6.0f, 0.0f), 1.0f);
        float ux = xr * (float)(D - 1);
        float fx = floorf(ux);
        s_ix0[t] = (int)fx;
        s_ix1[t] = (int)ceilf(ux);
        s_px0[t] = 1.0f - (ux - fx);      // ceil-floor in {0,1} -> dd = 1
    } else if (t >= 32 && t < 32 + G_POOL) {
        int j = t - 32;
        float yr = fminf(fmaxf(by1 + (float)j * (by2 - by1) / 6.0f, 0.0f), 1.0f);
        float uy = yr * (float)(D - 1);
        float fy = floorf(uy);
        s_iy0[j] = (int)fy;
        s_iy1[j] = (int)ceilf(uy);
        s_py0[j] = 1.0f - (uy - fy);
    }
    __syncthreads();

    // --- unique-coord masks ---
    if (t == 0) {
        unsigned long long mx = 0ull, my = 0ull;
#pragma unroll
        for (int i = 0; i < G_POOL; ++i) {
            mx |= (1ull << s_ix0[i]) | (1ull << s_ix1[i]);
            my |= (1ull << s_iy0[i]) | (1ull << s_iy1[i]);
        }
        s_mx = mx; s_my = my;
        int UYn = __popcll(my);
        s_UYn = UYn;
        s_P   = __popcll(mx) * UYn;
    }
    __syncthreads();

    const unsigned long long mx = s_mx, my = s_my;
    const int UYn = s_UYn, P = s_P;

    // --- gather index table: patch slot (u,v) -> plane offset X[u]*D + Y[v]
    if (t < P) {
        int u = t / UYn, v = t - u * UYn;
        s_gidx[t] = nth_set_bit(mx, u) * D + nth_set_bit(my, v);
    }

    // --- per-thread cell meta (all in registers) ---
    const int c0  = t / CELLS;            // 0..3
    const int pos = t - c0 * CELLS;
    const int i   = pos / G_POOL;
    const int j   = pos - i * G_POOL;
    const int ix0 = s_ix0[i], ix1 = s_ix1[i];
    const int iy0 = s_iy0[j], iy1 = s_iy1[j];
    const float px0 = s_px0[i], py0 = s_py0[j];
    const int a0 = __popcll(mx & ((1ull << ix0) - 1ull));
    const int a1 = __popcll(mx & ((1ull << ix1) - 1ull));
    const int b0 = __popcll(my & ((1ull << iy0) - 1ull));
    const int b1 = __popcll(my & ((1ull << iy1) - 1ull));
    const int o00 = a0 * UYn + b0, o10 = a1 * UYn + b0;
    const int o01 = a0 * UYn + b1, o11 = a1 * UYn + b1;
    const float px1 = 1.0f - px0, py1 = 1.0f - py0;
    const float w00 = px0 * py0, w10 = px1 * py0;
    const float w01 = px0 * py1, w11 = px1 * py1;

    __syncthreads();   // s_gidx ready

    const int NTOT = CHUNK * P;

#pragma unroll 1
    for (int chunk = 0; chunk < 2; ++chunk) {
        const int ch0 = chunk * CHUNK;

        // ---- coalesced gather: s_patch[p][cc] = ftrans[gbase+gidx[p]][ch0+cc]
        {
            const float* gsrc = g_ftrans + (size_t)gbase * NCH + ch0;
            for (int k = t; k < NTOT; k += TPB) {
                int pp = k >> 7, cc = k & 127;
                s_patch[pp * CPAD + cc] = __ldg(gsrc + s_gidx[pp] * NCH + cc);
            }
        }
        __syncthreads();

        // ---- sample: fixed cell, 4 channels per LDS.128, 8 passes x 16 ch
        const float4* q00 = (const float4*)(s_patch + o00 * CPAD);
        const float4* q10 = (const float4*)(s_patch + o10 * CPAD);
        const float4* q01 = (const float4*)(s_patch + o01 * CPAD);
        const float4* q11 = (const float4*)(s_patch + o11 * CPAD);

        float* op = out + (size_t)n * (NCH * CELLS) + ch0 * CELLS + t + 3 * CELLS * c0;
        // note: t + 3*49*c0 == (4*c0)*49 + pos

#pragma unroll
        for (int e = 0; e < 8; ++e) {
            const int fi = c0 + 4 * e;          // channels 4*(c0+4e) .. +3
            float4 v00 = q00[fi];
            float4 v10 = q10[fi];
            float4 v01 = q01[fi];
            float4 v11 = q11[fi];
            float r0 = w00 * v00.x + w10 * v10.x + w01 * v01.x + w11 * v11.x;
            float r1 = w00 * v00.y + w10 * v10.y + w01 * v01.y + w11 * v11.y;
            float r2 = w00 * v00.z + w10 * v10.z + w01 * v01.z + w11 * v11.z;
            float r3 = w00 * v00.w + w10 * v10.w + w01 * v01.w + w11 * v11.w;
            op[0]         = r0;
            op[CELLS]     = r1;
            op[2 * CELLS] = r2;
            op[3 * CELLS] = r3;
            op += 16 * CELLS;                   // next 16 channels
        }
        __syncthreads();   // protect s_patch before next chunk's gather
    }
}

extern "C" void kernel_launch(void* const* d_in, const int* in_sizes, int n_in,
                              void* d_out, int out_size)
{
    const int N = in_sizes[0] / 4;
    transpose_fmaps_kernel<<<NPOS, NCH>>>(
        (const float*)d_in[1], (const float*)d_in[2], (const float*)d_in[3],
        (const float*)d_in[4], (const float*)d_in[5], (const float*)d_in[6]);
    roialign_banks_kernel<<<N, TPB>>>(
        (const float*)d_in[0], (float*)d_out);
}

// round 9
// speedup vs baseline: 2.1111x; 1.1745x over previous
#include <cuda_runtime.h>
#include <math.h>

// RoIAlign_withBanks: N=2000 boxes, C=256, G=7, 6 FPN levels, dims {38,19,10,5,3,1}.
// Output [N, C, 7, 7] fp32.
//
// R8/R9 = R7 (transpose + dedup-gather) with: PCAP 48 (smem 25.5KB -> 8 blk/SM),
// float4 gather (LDG.128/STS.128), per-thread redundant mask computation
// (drops one barrier + t==0 serialization).
//  Kernel 1: transpose all fmaps [C,D,D] -> g_ftrans[pos][C] (2MB scratch).
//  Kernel 2: per box, grid touches only P (<=42 proven) unique fmap points.
//    Gather P x 128-ch chunks into shared (vectorized, coalesced), sample with
//    register-resident corner offsets + folded weights: 1 LDS.128 + 16 FFMA +
//    4 coalesced STG per 4 output elements.

#define G_POOL 7
#define CELLS  49
#define NCH    256
#define TPB    196
#define PCAP   48          // max unique patch points (math bound 42)
#define CPAD   132         // padded channel stride in floats (33 float4s)
#define CHUNK  128         // channels per chunk
#define NPOS   1940        // 1444+361+100+25+9+1

__device__ __align__(16) float g_ftrans[NPOS * NCH];   // [pos][channel]

__global__ void transpose_fmaps_kernel(
    const float* __restrict__ f0, const float* __restrict__ f1,
    const float* __restrict__ f2, const float* __restrict__ f3,
    const float* __restrict__ f4, const float* __restrict__ f5)
{
    const int p = blockIdx.x;          // global position index
    const float* fm; int DD, lp;
    if      (p < 1444) { fm = f0; DD = 1444; lp = p; }
    else if (p < 1805) { fm = f1; DD = 361;  lp = p - 1444; }
    else if (p < 1905) { fm = f2; DD = 100;  lp = p - 1805; }
    else if (p < 1930) { fm = f3; DD = 25;   lp = p - 1905; }
    else if (p < 1939) { fm = f4; DD = 9;    lp = p - 1930; }
    else               { fm = f5; DD = 1;    lp = 0; }
    g_ftrans[p * NCH + threadIdx.x] = fm[threadIdx.x * DD + lp];
}

__device__ __forceinline__ int nth_set_bit(unsigned long long m, int n) {
    for (int k = 0; k < n; ++k) m &= m - 1;
    return __ffsll(m) - 1;
}

__global__ __launch_bounds__(TPB) void roialign_banks_kernel(
    const float* __restrict__ boxes,
    float* __restrict__ out)
{
    __shared__ __align__(16) float s_patch[PCAP * CPAD];   // 25344 B
    __shared__ int   s_gidx[PCAP];
    __shared__ int   s_ix0[G_POOL], s_ix1[G_POOL], s_iy0[G_POOL], s_iy1[G_POOL];
    __shared__ float s_px0[G_POOL], s_py0[G_POOL];

    const int n = blockIdx.x;
    const int t = threadIdx.x;

    const float bx1 = boxes[4 * n + 0];
    const float by1 = boxes[4 * n + 1];
    const float bx2 = boxes[4 * n + 2];
    const float by2 = boxes[4 * n + 3];

    // Level: clip(floor(5 + log2(sqrt(w*h))), 0, 5)
    const float avg = sqrtf((bx2 - bx1) * (by2 - by1));
    const float lf  = floorf(5.0f + log2f(avg));
    const int lvl   = (int)fminf(fmaxf(lf, 0.0f), 5.0f);

    int D, gbase;
    switch (lvl) {
        case 0:  D = 38; gbase = 0;    break;
        case 1:  D = 19; gbase = 1444; break;
        case 2:  D = 10; gbase = 1805; break;
        case 3:  D = 5;  gbase = 1905; break;
        case 4:  D = 3;  gbase = 1930; break;
        default: D = 1;  gbase = 1939; break;
    }

    // --- per-axis grid coords (two warps in parallel) ---
    if (t < G_POOL) {
        float xr = fminf(fmaxf(bx1 + (float)t * (bx2 - bx1) / 6.0f, 0.0f), 1.0f);
        float ux = xr * (float)(D - 1);
        float fx = floorf(ux);
        s_ix0[t] = (int)fx;
        s_ix1[t] = (int)ceilf(ux);
        s_px0[t] = 1.0f - (ux - fx);      // ceil-floor in {0,1} -> dd = 1
    } else if (t >= 32 && t < 32 + G_POOL) {
        int j = t - 32;
        float yr = fminf(fmaxf(by1 + (float)j * (by2 - by1) / 6.0f, 0.0f), 1.0f);
        float uy = yr * (float)(D - 1);
        float fy = floorf(uy);
        s_iy0[j] = (int)fy;
        s_iy1[j] = (int)ceilf(uy);
        s_py0[j] = 1.0f - (uy - fy);
    }
    __syncthreads();

    // --- unique-coord masks: every thread computes redundantly (broadcast LDS)
    unsigned long long mx = 0ull, my = 0ull;
#pragma unroll
    for (int i = 0; i < G_POOL; ++i) {
        mx |= (1ull << s_ix0[i]) | (1ull << s_ix1[i]);
        my |= (1ull << s_iy0[i]) | (1ull << s_iy1[i]);
    }
    const int UYn = __popcll(my);
    const int P   = __popcll(mx) * UYn;

    // --- gather index table: patch slot (u,v) -> plane offset X[u]*D + Y[v]
    if (t < P) {
        int u = t / UYn, v = t - u * UYn;
        s_gidx[t] = nth_set_bit(mx, u) * D + nth_set_bit(my, v);
    }

    // --- per-thread cell meta (all in registers) ---
    const int c0  = t / CELLS;            // 0..3
    const int pos = t - c0 * CELLS;
    const int i   = pos / G_POOL;
    const int j   = pos - i * G_POOL;
    const int ix0 = s_ix0[i], ix1 = s_ix1[i];
    const int iy0 = s_iy0[j], iy1 = s_iy1[j];
    const float px0 = s_px0[i], py0 = s_py0[j];
    const int a0 = __popcll(mx & ((1ull << ix0) - 1ull));
    const int a1 = __popcll(mx & ((1ull << ix1) - 1ull));
    const int b0 = __popcll(my & ((1ull << iy0) - 1ull));
    const int b1 = __popcll(my & ((1ull << iy1) - 1ull));
    const int o00 = a0 * UYn + b0, o10 = a1 * UYn + b0;
    const int o01 = a0 * UYn + b1, o11 = a1 * UYn + b1;
    const float px1 = 1.0f - px0, py1 = 1.0f - py0;
    const float w00 = px0 * py0, w10 = px1 * py0;
    const float w01 = px0 * py1, w11 = px1 * py1;

    __syncthreads();   // s_gidx ready

    const int NT4 = (CHUNK / 4) * P;      // float4 words per chunk (32*P)

#pragma unroll 1
    for (int chunk = 0; chunk < 2; ++chunk) {
        const int ch0 = chunk * CHUNK;

        // ---- vectorized gather: s_patch[p][cc4] = ftrans[gbase+gidx[p]][ch0+4cc4..]
        {
            const float4* gsrc = (const float4*)g_ftrans
                               + (size_t)gbase * (NCH / 4) + (ch0 / 4);
            float4* sp = (float4*)s_patch;
            for (int k = t; k < NT4; k += TPB) {
                int pp = k >> 5, cc = k & 31;
                sp[pp * (CPAD / 4) + cc] = gsrc[s_gidx[pp] * (NCH / 4) + cc];
            }
        }
        __syncthreads();

        // ---- sample: fixed cell, 4 channels per LDS.128, 8 passes x 16 ch
        const float4* q00 = (const float4*)(s_patch + o00 * CPAD);
        const float4* q10 = (const float4*)(s_patch + o10 * CPAD);
        const float4* q01 = (const float4*)(s_patch + o01 * CPAD);
        const float4* q11 = (const float4*)(s_patch + o11 * CPAD);

        float* op = out + (size_t)n * (NCH * CELLS) + ch0 * CELLS + t + 3 * CELLS * c0;
        // note: t + 3*49*c0 == (4*c0)*49 + pos

#pragma unroll
        for (int e = 0; e < 8; ++e) {
            const int fi = c0 + 4 * e;          // channels 4*(c0+4e) .. +3
            float4 v00 = q00[fi];
            float4 v10 = q10[fi];
            float4 v01 = q01[fi];
            float4 v11 = q11[fi];
            float r0 = w00 * v00.x + w10 * v10.x + w01 * v01.x + w11 * v11.x;
            float r1 = w00 * v00.y + w10 * v10.y + w01 * v01.y + w11 * v11.y;
            float r2 = w00 * v00.z + w10 * v10.z + w01 * v01.z + w11 * v11.z;
            float r3 = w00 * v00.w + w10 * v10.w + w01 * v01.w + w11 * v11.w;
            op[0]         = r0;
            op[CELLS]     = r1;
            op[2 * CELLS] = r2;
            op[3 * CELLS] = r3;
            op += 16 * CELLS;                   // next 16 channels
        }
        __syncthreads();   // protect s_patch before next chunk's gather
    }
}

extern "C" void kernel_launch(void* const* d_in, const int* in_sizes, int n_in,
                              void* d_out, int out_size)
{
    const int N = in_sizes[0] / 4;
    transpose_fmaps_kernel<<<NPOS, NCH>>>(
        (const float*)d_in[1], (const float*)d_in[2], (const float*)d_in[3],
        (const float*)d_in[4], (const float*)d_in[5], (const float*)d_in[6]);
    roialign_banks_kernel<<<N, TPB>>>(
        (const float*)d_in[0], (float*)d_out);
}

// round 10
// speedup vs baseline: 2.1910x; 1.0378x over previous
#include <cuda_runtime.h>
#include <math.h>

// RoIAlign_withBanks: N=2000 boxes, C=256, G=7, 6 FPN levels, dims {38,19,10,5,3,1}.
// Output [N, C, 7, 7] fp32.
//
// R10 = R9 (transpose + dedup-gather, float4 everywhere) + software-pipelined
// double-buffered patch: 4 chunks of 64 channels; while sampling chunk k from
// buffer k&1, chunk k+1's patch is already in registers (LDG issued pre-sample)
// and is stored to the other buffer after sampling -> L2 gather latency hides
// behind compute instead of serializing at a barrier.

#define G_POOL 7
#define CELLS  49
#define NCH    256
#define TPB    196
#define PCAP   48          // max unique patch points (math bound 42)
#define CPAD   68          // padded floats per point for 64-ch chunk (17 float4)
#define NPOS   1940        // 1444+361+100+25+9+1

__device__ __align__(16) float g_ftrans[NPOS * NCH];   // [pos][channel]

__global__ void transpose_fmaps_kernel(
    const float* __restrict__ f0, const float* __restrict__ f1,
    const float* __restrict__ f2, const float* __restrict__ f3,
    const float* __restrict__ f4, const float* __restrict__ f5)
{
    const int p = blockIdx.x;
    const float* fm; int DD, lp;
    if      (p < 1444) { fm = f0; DD = 1444; lp = p; }
    else if (p < 1805) { fm = f1; DD = 361;  lp = p - 1444; }
    else if (p < 1905) { fm = f2; DD = 100;  lp = p - 1805; }
    else if (p < 1930) { fm = f3; DD = 25;   lp = p - 1905; }
    else if (p < 1939) { fm = f4; DD = 9;    lp = p - 1930; }
    else               { fm = f5; DD = 1;    lp = 0; }
    g_ftrans[p * NCH + threadIdx.x] = fm[threadIdx.x * DD + lp];
}

__device__ __forceinline__ int nth_set_bit(unsigned long long m, int n) {
    for (int k = 0; k < n; ++k) m &= m - 1;
    return __ffsll(m) - 1;
}

__global__ __launch_bounds__(TPB) void roialign_banks_kernel(
    const float* __restrict__ boxes,
    float* __restrict__ out)
{
    __shared__ __align__(16) float s_patch[2][PCAP * CPAD];   // 2 x 13056 B
    __shared__ int   s_gidx[PCAP];
    __shared__ int   s_ix0[G_POOL], s_ix1[G_POOL], s_iy0[G_POOL], s_iy1[G_POOL];
    __shared__ float s_px0[G_POOL], s_py0[G_POOL];

    const int n = blockIdx.x;
    const int t = threadIdx.x;

    const float bx1 = boxes[4 * n + 0];
    const float by1 = boxes[4 * n + 1];
    const float bx2 = boxes[4 * n + 2];
    const float by2 = boxes[4 * n + 3];

    // Level: clip(floor(5 + log2(sqrt(w*h))), 0, 5)
    const float avg = sqrtf((bx2 - bx1) * (by2 - by1));
    const float lf  = floorf(5.0f + log2f(avg));
    const int lvl   = (int)fminf(fmaxf(lf, 0.0f), 5.0f);

    int D, gbase;
    switch (lvl) {
        case 0:  D = 38; gbase = 0;    break;
        case 1:  D = 19; gbase = 1444; break;
        case 2:  D = 10; gbase = 1805; break;
        case 3:  D = 5;  gbase = 1905; break;
        case 4:  D = 3;  gbase = 1930; break;
        default: D = 1;  gbase = 1939; break;
    }

    // --- per-axis grid coords (two warps in parallel) ---
    if (t < G_POOL) {
        float xr = fminf(fmaxf(bx1 + (float)t * (bx2 - bx1) / 6.0f, 0.0f), 1.0f);
        float ux = xr * (float)(D - 1);
        float fx = floorf(ux);
        s_ix0[t] = (int)fx;
        s_ix1[t] = (int)ceilf(ux);
        s_px0[t] = 1.0f - (ux - fx);      // ceil-floor in {0,1} -> dd = 1
    } else if (t >= 32 && t < 32 + G_POOL) {
        int j = t - 32;
        float yr = fminf(fmaxf(by1 + (float)j * (by2 - by1) / 6.0f, 0.0f), 1.0f);
        float uy = yr * (float)(D - 1);
        float fy = floorf(uy);
        s_iy0[j] = (int)fy;
        s_iy1[j] = (int)ceilf(uy);
        s_py0[j] = 1.0f - (uy - fy);
    }
    __syncthreads();

    // --- unique-coord masks: redundant per-thread (broadcast LDS) ---
    unsigned long long mx = 0ull, my = 0ull;
#pragma unroll
    for (int i = 0; i < G_POOL; ++i) {
        mx |= (1ull << s_ix0[i]) | (1ull << s_ix1[i]);
        my |= (1ull << s_iy0[i]) | (1ull << s_iy1[i]);
    }
    const int UYn = __popcll(my);
    const int P   = __popcll(mx) * UYn;

    // --- gather index table: patch slot (u,v) -> plane offset X[u]*D + Y[v]
    if (t < P) {
        int u = t / UYn, v = t - u * UYn;
        s_gidx[t] = nth_set_bit(mx, u) * D + nth_set_bit(my, v);
    }

    // --- per-thread cell meta (registers) ---
    const int c0  = t / CELLS;            // 0..3
    const int pos = t - c0 * CELLS;
    const int i   = pos / G_POOL;
    const int j   = pos - i * G_POOL;
    const int ix0 = s_ix0[i], ix1 = s_ix1[i];
    const int iy0 = s_iy0[j], iy1 = s_iy1[j];
    const float px0 = s_px0[i], py0 = s_py0[j];
    const int a0 = __popcll(mx & ((1ull << ix0) - 1ull));
    const int a1 = __popcll(mx & ((1ull << ix1) - 1ull));
    const int b0 = __popcll(my & ((1ull << iy0) - 1ull));
    const int b1 = __popcll(my & ((1ull << iy1) - 1ull));
    const int o00 = a0 * UYn + b0, o10 = a1 * UYn + b0;
    const int o01 = a0 * UYn + b1, o11 = a1 * UYn + b1;
    const float px1 = 1.0f - px0, py1 = 1.0f - py0;
    const float w00 = px0 * py0, w10 = px1 * py0;
    const float w01 = px0 * py1, w11 = px1 * py1;

    __syncthreads();   // s_gidx ready

    const float4* gt  = (const float4*)g_ftrans + (size_t)gbase * (NCH / 4);
    const int     nt4 = (NCH / 4 / 4) * P;        // 16 float4 per point per chunk
    float* const  outn = out + (size_t)n * (NCH * CELLS) + 147 * c0 + t;

    // ---- initial gather: chunk 0 into buffer 0 ----
    {
        float4* db = (float4*)s_patch[0];
        for (int idx = t; idx < nt4; idx += TPB) {
            int pp = idx >> 4, cc = idx & 15;
            db[pp * (CPAD / 4) + cc] = gt[s_gidx[pp] * (NCH / 4) + cc];
        }
    }
    __syncthreads();

#pragma unroll
    for (int k = 0; k < 4; ++k) {
        // ---- prefetch chunk k+1 into registers (LDG issued before sampling)
        float4 pf0, pf1;
        bool h0 = false, h1 = false;
        if (k < 3) {
            const float4* gs = gt + (k + 1) * 16;
            if (t < nt4)       { pf0 = gs[s_gidx[t >> 4] * (NCH / 4) + (t & 15)]; h0 = true; }
            int i1 = t + TPB;
            if (i1 < nt4)      { pf1 = gs[s_gidx[i1 >> 4] * (NCH / 4) + (i1 & 15)]; h1 = true; }
        }

        // ---- sample chunk k from buffer k&1 ----
        {
            const float* buf = s_patch[k & 1];
            const float4* q00 = (const float4*)(buf + o00 * CPAD);
            const float4* q10 = (const float4*)(buf + o10 * CPAD);
            const float4* q01 = (const float4*)(buf + o01 * CPAD);
            const float4* q11 = (const float4*)(buf + o11 * CPAD);
            float* op = outn + k * 64 * CELLS;
#pragma unroll
            for (int e = 0; e < 4; ++e) {
                const int fi = c0 + 4 * e;       // channels 4*fi..+3 of chunk
                float4 v00 = q00[fi];
                float4 v10 = q10[fi];
                float4 v01 = q01[fi];
                float4 v11 = q11[fi];
                float r0 = w00 * v00.x + w10 * v10.x + w01 * v01.x + w11 * v11.x;
                float r1 = w00 * v00.y + w10 * v10.y + w01 * v01.y + w11 * v11.y;
                float r2 = w00 * v00.z + w10 * v10.z + w01 * v01.z + w11 * v11.z;
                float r3 = w00 * v00.w + w10 * v10.w + w01 * v01.w + w11 * v11.w;
                op[0]         = r0;
                op[CELLS]     = r1;
                op[2 * CELLS] = r2;
                op[3 * CELLS] = r3;
                op += 16 * CELLS;                // next 16 channels
            }
        }

        // ---- commit prefetched chunk k+1 into the other buffer ----
        if (k < 3) {
            float4* db = (float4*)s_patch[(k + 1) & 1];
            if (h0) db[(t >> 4) * (CPAD / 4) + (t & 15)] = pf0;
            if (h1) { int i1 = t + TPB; db[(i1 >> 4) * (CPAD / 4) + (i1 & 15)] = pf1; }
            // rare tail (P > 24): direct gather, not overlapped
            const float4* gs = gt + (k + 1) * 16;
            for (int idx = t + 2 * TPB; idx < nt4; idx += TPB)
                db[(idx >> 4) * (CPAD / 4) + (idx & 15)] =
                    gs[s_gidx[idx >> 4] * (NCH / 4) + (idx & 15)];
            __syncthreads();
        }
    }
}

extern "C" void kernel_launch(void* const* d_in, const int* in_sizes, int n_in,
                              void* d_out, int out_size)
{
    const int N = in_sizes[0] / 4;
    transpose_fmaps_kernel<<<NPOS, NCH>>>(
        (const float*)d_in[1], (const float*)d_in[2], (const float*)d_in[3],
        (const float*)d_in[4], (const float*)d_in[5], (const float*)d_in[6]);
    roialign_banks_kernel<<<N, TPB>>>(
        (const float*)d_in[0], (float*)d_out);
}